// round 1
// baseline (speedup 1.0000x reference)
#include <cuda_runtime.h>

// EvroModel: x[131072,256] -> relu(x@w1+b1)[.,64] -> tanh(@w2+b2)[.,16] -> @w3+b3 [.,4]
// -> softmax over the ENTIRE flattened [131072*4] tensor.
//
// Round 1: fp32 FFMA baseline near the FMA-pipe roofline.
//  - w1 (64KB) + w2/w3/biases staged in dynamic SMEM (broadcast LDS.128)
//  - 1 thread per row, 64 fp32 accumulators in registers
//  - global softmax WITHOUT max subtraction (logits bounded ~|20|, exp is fp32-safe)
//  - deterministic reduction (no float atomics): block partials -> 1-block tree -> scale

#define B_ROWS 131072
#define TPB 256
#define NBLK (B_ROWS / TPB)   // 512

__device__ float g_partials[NBLK];
__device__ float g_inv_sum;

// dynamic smem layout (floats):
//   [0,16384)        w1  (256x64)
//   [16384,17408)    w2  (64x16)
//   [17408,17472)    b1  (64)
//   [17472,17488)    b2  (16)
//   [17488,17552)    w3  (16x4)
//   [17552,17556)    b3  (4)
#define SM_FLOATS 17556

__global__ __launch_bounds__(TPB, 2)
void mlp_kernel(const float* __restrict__ x,
                const float* __restrict__ w1, const float* __restrict__ b1,
                const float* __restrict__ w2, const float* __restrict__ b2,
                const float* __restrict__ w3, const float* __restrict__ b3,
                float* __restrict__ out)
{
    extern __shared__ float sm[];
    float* sw1 = sm;            // 16384
    float* sw2 = sm + 16384;    // 1024
    float* sb1 = sm + 17408;    // 64
    float* sb2 = sm + 17472;    // 16
    float* sw3 = sm + 17488;    // 64
    float* sb3 = sm + 17552;    // 4
    __shared__ float red[TPB];

    const int tid = threadIdx.x;

    // Stage weights cooperatively (vectorized where possible).
    {
        const float4* w1v = (const float4*)w1;
        float4* sw1v = (float4*)sw1;
        #pragma unroll 4
        for (int i = tid; i < 4096; i += TPB) sw1v[i] = w1v[i];
        const float4* w2v = (const float4*)w2;
        float4* sw2v = (float4*)sw2;
        for (int i = tid; i < 256; i += TPB) sw2v[i] = w2v[i];
        if (tid < 64) sb1[tid] = b1[tid];
        if (tid < 16) sb2[tid] = b2[tid];
        if (tid < 64) sw3[tid] = w3[tid];
        if (tid < 4)  sb3[tid] = b3[tid];
    }
    __syncthreads();

    const int row = blockIdx.x * TPB + tid;
    const float4* xr = (const float4*)(x + (size_t)row * 256);

    // ---- layer 1: acc[64] = b1 + x(row,:) @ w1 ----
    float acc[64];
    #pragma unroll
    for (int j = 0; j < 64; j++) acc[j] = sb1[j];

    float4 xv = __ldg(&xr[0]);
    #pragma unroll 1
    for (int k4 = 0; k4 < 64; k4++) {
        float4 xn = __ldg(&xr[(k4 + 1) & 63]);   // prefetch (wrap on last iter, harmless)
        const float* wr = &sw1[(k4 * 4) * 64];
        #pragma unroll
        for (int j = 0; j < 64; j++) acc[j] = fmaf(xv.x, wr[j], acc[j]);
        #pragma unroll
        for (int j = 0; j < 64; j++) acc[j] = fmaf(xv.y, wr[64 + j], acc[j]);
        #pragma unroll
        for (int j = 0; j < 64; j++) acc[j] = fmaf(xv.z, wr[128 + j], acc[j]);
        #pragma unroll
        for (int j = 0; j < 64; j++) acc[j] = fmaf(xv.w, wr[192 + j], acc[j]);
        xv = xn;
    }

    // ---- layer 2: h2[16] = tanh(b2 + relu(acc) @ w2) ----
    float h2[16];
    #pragma unroll
    for (int j = 0; j < 16; j++) h2[j] = sb2[j];
    #pragma unroll
    for (int i = 0; i < 64; i++) {
        float h = fmaxf(acc[i], 0.0f);
        const float* wr = &sw2[i * 16];
        #pragma unroll
        for (int j = 0; j < 16; j++) h2[j] = fmaf(h, wr[j], h2[j]);
    }
    #pragma unroll
    for (int j = 0; j < 16; j++) h2[j] = tanhf(h2[j]);

    // ---- layer 3: logits[4] = b3 + h2 @ w3 ----
    float lg[4];
    #pragma unroll
    for (int j = 0; j < 4; j++) lg[j] = sb3[j];
    #pragma unroll
    for (int i = 0; i < 16; i++) {
        float h = h2[i];
        const float* wr = &sw3[i * 4];
        #pragma unroll
        for (int j = 0; j < 4; j++) lg[j] = fmaf(h, wr[j], lg[j]);
    }

    // exp (no max subtraction needed: |logit| <= sum|w3| + |b3| ~ 20)
    float e0 = __expf(lg[0]);
    float e1 = __expf(lg[1]);
    float e2 = __expf(lg[2]);
    float e3 = __expf(lg[3]);

    float4 ev; ev.x = e0; ev.y = e1; ev.z = e2; ev.w = e3;
    ((float4*)out)[row] = ev;

    // deterministic block-level partial sum of exp
    red[tid] = (e0 + e1) + (e2 + e3);
    __syncthreads();
    #pragma unroll
    for (int off = TPB / 2; off > 0; off >>= 1) {
        if (tid < off) red[tid] += red[tid + off];
        __syncthreads();
    }
    if (tid == 0) g_partials[blockIdx.x] = red[0];
}

__global__ void reduce_kernel()
{
    __shared__ float red[NBLK];
    const int tid = threadIdx.x;
    red[tid] = g_partials[tid];
    __syncthreads();
    #pragma unroll
    for (int off = NBLK / 2; off > 0; off >>= 1) {
        if (tid < off) red[tid] += red[tid + off];
        __syncthreads();
    }
    if (tid == 0) g_inv_sum = 1.0f / red[0];
}

__global__ void scale_kernel(float* __restrict__ out)
{
    const int i = blockIdx.x * blockDim.x + threadIdx.x;  // one float4 per thread
    const float inv = g_inv_sum;
    float4 v = ((float4*)out)[i];
    v.x *= inv; v.y *= inv; v.z *= inv; v.w *= inv;
    ((float4*)out)[i] = v;
}

extern "C" void kernel_launch(void* const* d_in, const int* in_sizes, int n_in,
                              void* d_out, int out_size)
{
    const float* x  = (const float*)d_in[0];
    const float* w1 = (const float*)d_in[1];
    const float* b1 = (const float*)d_in[2];
    const float* w2 = (const float*)d_in[3];
    const float* b2 = (const float*)d_in[4];
    const float* w3 = (const float*)d_in[5];
    const float* b3 = (const float*)d_in[6];
    float* out = (float*)d_out;

    const size_t smem = SM_FLOATS * sizeof(float);
    cudaFuncSetAttribute(mlp_kernel, cudaFuncAttributeMaxDynamicSharedMemorySize, (int)smem);

    mlp_kernel<<<NBLK, TPB, smem>>>(x, w1, b1, w2, b2, w3, b3, out);
    reduce_kernel<<<1, NBLK>>>();
    scale_kernel<<<(B_ROWS * 4) / (4 * 256), 256>>>(out);  // 512 blocks, 1 float4/thread
}